// round 2
// baseline (speedup 1.0000x reference)
#include <cuda_runtime.h>
#include <math.h>

// Fixed problem shape
#define BB       4
#define SQ       2048
#define SKV      2048
#define DMODEL   1024
#define NHEADS   16
#define HDIM     64

// Scratch (device globals; no allocation allowed)
__device__ float g_Q[BB * NHEADS * SQ * HDIM];     // [B,H,SQ,Dh]
__device__ float g_K[BB * NHEADS * SKV * HDIM];    // [B,H,SKV,Dh]
__device__ float g_V[BB * NHEADS * SKV * HDIM];    // [B,H,SKV,Dh]
__device__ float g_attn[BB * SQ * DMODEL];         // [B*SQ, D]

// ---------------------------------------------------------------------------
// GEMM: Y = X @ W^T + bias.  X:[M,1024] row-major, W:[1024,1024] row-major
// (row n holds W[n, :], contiguous over k).  N = K = 1024.
// LAYOUT 0: Y row-major [M,1024]
// LAYOUT 1: head split  Y[(((m/S)*16 + n/64)*S + m%S)*64 + n%64]
// 128x128 tile, BK=16, 256 threads, 8x8 micro-tile.
// ---------------------------------------------------------------------------
template <int LAYOUT>
__global__ __launch_bounds__(256)
void gemm_bias_kernel(const float* __restrict__ X, const float* __restrict__ W,
                      const float* __restrict__ bias, float* __restrict__ Y,
                      int S)
{
    __shared__ __align__(16) float As[16][132];
    __shared__ __align__(16) float Bs[16][132];

    const int tid = threadIdx.x;
    const int tx  = tid & 15;   // 0..15 -> n micro
    const int ty  = tid >> 4;   // 0..15 -> m micro
    const int m0  = blockIdx.y * 128;
    const int n0  = blockIdx.x * 128;

    float acc[8][8];
#pragma unroll
    for (int i = 0; i < 8; i++)
#pragma unroll
        for (int j = 0; j < 8; j++) acc[i][j] = 0.0f;

    for (int k0 = 0; k0 < 1024; k0 += 16) {
#pragma unroll
        for (int i = 0; i < 2; i++) {
            int v   = tid + (i << 8);
            int row = v >> 2;          // 0..127
            int kq  = (v & 3) << 2;    // 0,4,8,12
            const float4 xv = *reinterpret_cast<const float4*>(
                X + (size_t)(m0 + row) * 1024 + k0 + kq);
            As[kq + 0][row] = xv.x; As[kq + 1][row] = xv.y;
            As[kq + 2][row] = xv.z; As[kq + 3][row] = xv.w;
            const float4 wv = *reinterpret_cast<const float4*>(
                W + (size_t)(n0 + row) * 1024 + k0 + kq);
            Bs[kq + 0][row] = wv.x; Bs[kq + 1][row] = wv.y;
            Bs[kq + 2][row] = wv.z; Bs[kq + 3][row] = wv.w;
        }
        __syncthreads();

#pragma unroll
        for (int k = 0; k < 16; k++) {
            float4 a0 = *reinterpret_cast<const float4*>(&As[k][ty * 8]);
            float4 a1 = *reinterpret_cast<const float4*>(&As[k][ty * 8 + 4]);
            float4 b0 = *reinterpret_cast<const float4*>(&Bs[k][tx * 8]);
            float4 b1 = *reinterpret_cast<const float4*>(&Bs[k][tx * 8 + 4]);
            float a[8] = {a0.x, a0.y, a0.z, a0.w, a1.x, a1.y, a1.z, a1.w};
            float b[8] = {b0.x, b0.y, b0.z, b0.w, b1.x, b1.y, b1.z, b1.w};
#pragma unroll
            for (int i = 0; i < 8; i++)
#pragma unroll
                for (int j = 0; j < 8; j++)
                    acc[i][j] = fmaf(a[i], b[j], acc[i][j]);
        }
        __syncthreads();
    }

    float bb[8];
#pragma unroll
    for (int j = 0; j < 8; j++) bb[j] = bias[n0 + tx * 8 + j];

#pragma unroll
    for (int i = 0; i < 8; i++) {
        int m = m0 + ty * 8 + i;
#pragma unroll
        for (int jj = 0; jj < 2; jj++) {
            int n = n0 + tx * 8 + jj * 4;
            float4 r;
            r.x = acc[i][jj * 4 + 0] + bb[jj * 4 + 0];
            r.y = acc[i][jj * 4 + 1] + bb[jj * 4 + 1];
            r.z = acc[i][jj * 4 + 2] + bb[jj * 4 + 2];
            r.w = acc[i][jj * 4 + 3] + bb[jj * 4 + 3];
            size_t idx;
            if (LAYOUT == 0) {
                idx = (size_t)m * 1024 + n;
            } else {
                int b = m / S;
                int s = m - b * S;
                int h = n >> 6;
                int d = n & 63;
                idx = (((size_t)b * NHEADS + h) * S + s) * 64 + d;
            }
            *reinterpret_cast<float4*>(Y + idx) = r;
        }
    }
}

// ---------------------------------------------------------------------------
// Flash attention: per (b,h), out = softmax(Q K^T / 8) V
// Grid: (SQ/64, B*H). Block: 256 threads.
// BQ=64 q rows per CTA, BKV=32 kv rows per tile, Dh=64.
// Thread (ty=tid/16, tx=tid%16):
//   S micro-tile: rows ty*4..+4, cols tx*2..+2 (64x32)
//   O micro-tile: rows ty*4..+4, dh   tx*4..+4 (64x64)
// Smem: Qs transposed [d][r] (stride 68), KP holds Ks [d][c] (stride 36)
// then reused as Ps [c][r] (stride 68), Vs natural [c][d] (stride 64).
// ---------------------------------------------------------------------------
__global__ __launch_bounds__(256)
void attn_kernel(const float* __restrict__ Q, const float* __restrict__ K,
                 const float* __restrict__ V, float* __restrict__ out)
{
    __shared__ __align__(16) float Qs[64 * 68];   // 17408 B
    __shared__ __align__(16) float KP[64 * 36];   //  9216 B (Ks / Ps union)
    __shared__ __align__(16) float Vs[32 * 64];   //  8192 B

    const int tid = threadIdx.x;
    const int tx  = tid & 15;
    const int ty  = tid >> 4;
    const int ty4 = ty * 4;
    const int tx2 = tx * 2;
    const int tx4 = tx * 4;

    const int bh = blockIdx.y;          // b*16 + h
    const int q0 = blockIdx.x * 64;

    const float* Qp = Q + ((size_t)bh * SQ + q0) * 64;
    const float* Kp = K + (size_t)bh * SKV * 64;
    const float* Vp = V + (size_t)bh * SKV * 64;

    // Load Q tile (64x64) transposed into Qs[d][r]
#pragma unroll
    for (int i = 0; i < 4; i++) {
        int v  = tid + (i << 8);
        int r  = v >> 4;          // 0..63
        int dq = (v & 15) << 2;   // 0..60
        const float4 q4 = *reinterpret_cast<const float4*>(Qp + (size_t)r * 64 + dq);
        Qs[(dq + 0) * 68 + r] = q4.x;
        Qs[(dq + 1) * 68 + r] = q4.y;
        Qs[(dq + 2) * 68 + r] = q4.z;
        Qs[(dq + 3) * 68 + r] = q4.w;
    }

    float m_i[4], l_i[4], o[4][4];
#pragma unroll
    for (int i = 0; i < 4; i++) {
        m_i[i] = -1e30f;
        l_i[i] = 0.0f;
#pragma unroll
        for (int j = 0; j < 4; j++) o[i][j] = 0.0f;
    }
    const float scale = 0.125f;   // 1/sqrt(64)

    for (int t = 0; t < SKV / 32; t++) {
        __syncthreads();   // prior O-gemm done reading KP/Vs; Qs visible after 1st
        const float* Kt = Kp + (size_t)t * 32 * 64;
        const float* Vt = Vp + (size_t)t * 32 * 64;
#pragma unroll
        for (int i = 0; i < 2; i++) {
            int v  = tid + (i << 8);
            int c  = v >> 4;          // 0..31
            int dq = (v & 15) << 2;   // 0..60
            const float4 k4 = *reinterpret_cast<const float4*>(Kt + (size_t)c * 64 + dq);
            KP[(dq + 0) * 36 + c] = k4.x;
            KP[(dq + 1) * 36 + c] = k4.y;
            KP[(dq + 2) * 36 + c] = k4.z;
            KP[(dq + 3) * 36 + c] = k4.w;
            const float4 v4 = *reinterpret_cast<const float4*>(Vt + (size_t)c * 64 + dq);
            *reinterpret_cast<float4*>(&Vs[c * 64 + dq]) = v4;
        }
        __syncthreads();

        // S = Q K^T  (rows ty*4..+4, cols tx*2..+2)
        float s[4][2];
#pragma unroll
        for (int i = 0; i < 4; i++) { s[i][0] = 0.0f; s[i][1] = 0.0f; }
#pragma unroll
        for (int d = 0; d < 64; d++) {
            float4 a  = *reinterpret_cast<const float4*>(&Qs[d * 68 + ty4]);
            float2 bv = *reinterpret_cast<const float2*>(&KP[d * 36 + tx2]);
            float av[4] = {a.x, a.y, a.z, a.w};
#pragma unroll
            for (int i = 0; i < 4; i++) {
                s[i][0] = fmaf(av[i], bv.x, s[i][0]);
                s[i][1] = fmaf(av[i], bv.y, s[i][1]);
            }
        }

        // online softmax (row reductions over 16 tx lanes via shfl_xor)
        float mt[4];
#pragma unroll
        for (int i = 0; i < 4; i++) {
            s[i][0] *= scale; s[i][1] *= scale;
            mt[i] = fmaxf(s[i][0], s[i][1]);
        }
#pragma unroll
        for (int off = 1; off < 16; off <<= 1)
#pragma unroll
            for (int i = 0; i < 4; i++)
                mt[i] = fmaxf(mt[i], __shfl_xor_sync(0xffffffffu, mt[i], off));

        float p[4][2], rs[4], alpha[4];
#pragma unroll
        for (int i = 0; i < 4; i++) {
            float m_new = fmaxf(m_i[i], mt[i]);
            alpha[i] = __expf(m_i[i] - m_new);
            p[i][0] = __expf(s[i][0] - m_new);
            p[i][1] = __expf(s[i][1] - m_new);
            rs[i] = p[i][0] + p[i][1];
            m_i[i] = m_new;
        }
#pragma unroll
        for (int off = 1; off < 16; off <<= 1)
#pragma unroll
            for (int i = 0; i < 4; i++)
                rs[i] += __shfl_xor_sync(0xffffffffu, rs[i], off);
#pragma unroll
        for (int i = 0; i < 4; i++) {
            l_i[i] = l_i[i] * alpha[i] + rs[i];
#pragma unroll
            for (int j = 0; j < 4; j++) o[i][j] *= alpha[i];
        }

        __syncthreads();   // all threads done reading Ks from KP

        // write P transposed: Ps[c][r], stride 68
#pragma unroll
        for (int j = 0; j < 2; j++) {
            float4 pv = make_float4(p[0][j], p[1][j], p[2][j], p[3][j]);
            *reinterpret_cast<float4*>(&KP[(tx2 + j) * 68 + ty4]) = pv;
        }
        __syncthreads();

        // O += P V  (rows ty*4..+4, dh tx*4..+4)
#pragma unroll
        for (int c = 0; c < 32; c++) {
            float4 a  = *reinterpret_cast<const float4*>(&KP[c * 68 + ty4]);
            float4 bv = *reinterpret_cast<const float4*>(&Vs[c * 64 + tx4]);
            float av[4] = {a.x, a.y, a.z, a.w};
            float bb[4] = {bv.x, bv.y, bv.z, bv.w};
#pragma unroll
            for (int i = 0; i < 4; i++)
#pragma unroll
                for (int j = 0; j < 4; j++)
                    o[i][j] = fmaf(av[i], bb[j], o[i][j]);
        }
    }

    // epilogue: normalize and write to attn buffer [B*SQ, 1024]
    const int b = bh >> 4;
    const int h = bh & 15;
    const size_t row_base = (size_t)b * SQ + q0 + ty4;
#pragma unroll
    for (int i = 0; i < 4; i++) {
        float inv = 1.0f / l_i[i];
        float4 r = make_float4(o[i][0] * inv, o[i][1] * inv,
                               o[i][2] * inv, o[i][3] * inv);
        *reinterpret_cast<float4*>(out + (row_base + i) * 1024 + h * 64 + tx4) = r;
    }
}

// ---------------------------------------------------------------------------
extern "C" void kernel_launch(void* const* d_in, const int* in_sizes, int n_in,
                              void* d_out, int out_size)
{
    (void)in_sizes; (void)n_in; (void)out_size;
    const float* query = (const float*)d_in[0];
    const float* keyval = (const float*)d_in[1];
    const float* Wq = (const float*)d_in[2];
    const float* bq = (const float*)d_in[3];
    const float* Wk = (const float*)d_in[4];
    const float* bk = (const float*)d_in[5];
    const float* Wv = (const float*)d_in[6];
    const float* bv = (const float*)d_in[7];
    const float* Wo = (const float*)d_in[8];
    const float* bo = (const float*)d_in[9];
    float* out = (float*)d_out;

    float *qbuf, *kbuf, *vbuf, *abuf;
    cudaGetSymbolAddress((void**)&qbuf, g_Q);
    cudaGetSymbolAddress((void**)&kbuf, g_K);
    cudaGetSymbolAddress((void**)&vbuf, g_V);
    cudaGetSymbolAddress((void**)&abuf, g_attn);

    dim3 blk(256);
    dim3 grid_proj(8, (BB * SQ) / 128);   // (8, 64)

    gemm_bias_kernel<1><<<grid_proj, blk>>>(query,  Wq, bq, qbuf, SQ);
    gemm_bias_kernel<1><<<grid_proj, blk>>>(keyval, Wk, bk, kbuf, SKV);
    gemm_bias_kernel<1><<<grid_proj, blk>>>(keyval, Wv, bv, vbuf, SKV);

    dim3 grid_attn(SQ / 64, BB * NHEADS); // (32, 64)
    attn_kernel<<<grid_attn, blk>>>(qbuf, kbuf, vbuf, abuf);

    gemm_bias_kernel<0><<<grid_proj, blk>>>(abuf, Wo, bo, out, SQ);
}

// round 4
// speedup vs baseline: 1.3968x; 1.3968x over previous
#include <cuda_runtime.h>
#include <cstdint>
#include <math.h>

// Fixed problem shape
#define BB       4
#define SQ       2048
#define SKV      2048
#define DMODEL   1024
#define NHEADS   16
#define HDIM     64

// Scratch (device globals; no allocation allowed)
__device__ float g_Q[BB * NHEADS * SQ * HDIM];     // [B,H,SQ,Dh]
__device__ float g_K[BB * NHEADS * SKV * HDIM];    // [B,H,SKV,Dh]
__device__ float g_V[BB * NHEADS * SKV * HDIM];    // [B,H,SKV,Dh]
__device__ float g_attn[BB * SQ * DMODEL];         // [B*SQ, D]

// ===========================================================================
// Helpers: tf32 round, ldmatrix, mma (all base-target PTX, sm_80+)
// ===========================================================================
__device__ __forceinline__ float to_tf32(float x) {
    uint32_t r;
    asm("cvt.rna.tf32.f32 %0, %1;" : "=r"(r) : "f"(x));
    return __uint_as_float(r);
}

__device__ __forceinline__ void ldmatrix_x4(uint32_t& r0, uint32_t& r1,
                                            uint32_t& r2, uint32_t& r3,
                                            uint32_t addr) {
    asm volatile("ldmatrix.sync.aligned.m8n8.x4.shared.b16 {%0,%1,%2,%3}, [%4];"
                 : "=r"(r0), "=r"(r1), "=r"(r2), "=r"(r3) : "r"(addr));
}

__device__ __forceinline__ void mma_tf32(float& c0, float& c1, float& c2, float& c3,
                                         uint32_t a0, uint32_t a1, uint32_t a2, uint32_t a3,
                                         uint32_t b0, uint32_t b1) {
    asm volatile(
        "mma.sync.aligned.m16n8k8.row.col.f32.tf32.tf32.f32 "
        "{%0,%1,%2,%3}, {%4,%5,%6,%7}, {%8,%9}, {%0,%1,%2,%3};"
        : "+f"(c0), "+f"(c1), "+f"(c2), "+f"(c3)
        : "r"(a0), "r"(a1), "r"(a2), "r"(a3), "r"(b0), "r"(b1));
}

__device__ __forceinline__ uint32_t smem_u32(const void* p) {
    return (uint32_t)__cvta_generic_to_shared(p);
}

// XOR swizzle on 16B chunks within a 128B row (rows of 32 f32)
__device__ __forceinline__ uint32_t swz(uint32_t off) {
    return off ^ ((off >> 3) & 0x70);
}

// ===========================================================================
// HMMA tf32 GEMM: Y = X @ W^T + bias.
// X:[M,1024] row-major, W:[1024,1024] row-major (row n = W[n,:]).
// CTA 128x128, BK=32, 8 warps (2m x 4n), warp tile 64x32.
// LAYOUT 0: Y row-major [M,1024]
// LAYOUT 1: head split  Y[(((m/S)*16 + n/64)*S + m%S)*64 + n%64]
// ===========================================================================
#define GK 32                       // BK floats
#define TILE_BYTES (128 * GK * 4)   // 16384 per operand per buffer
#define SM_TOTAL_G (4 * TILE_BYTES) // 65536

template <int LAYOUT>
__global__ __launch_bounds__(256)
void gemm_hmma_kernel(const float* __restrict__ X, const float* __restrict__ W,
                      const float* __restrict__ bias, float* __restrict__ Y, int S)
{
    extern __shared__ __align__(128) char smem[];
    // layout: As0 | Bs0 | As1 | Bs1
    const uint32_t sbase = smem_u32(smem);

    const int tid  = threadIdx.x;
    const int wid  = tid >> 5;
    const int lane = tid & 31;
    const int wm   = wid >> 2;        // 0..1
    const int wn   = wid & 3;         // 0..3
    const int m0   = blockIdx.y * 128;
    const int n0   = blockIdx.x * 128;

    // ldmatrix per-thread source rows (byte offsets into tile)
    const uint32_t arow_b = (uint32_t)(wm * 64 + (lane & 15)) * 128;
    const uint32_t achk   = (uint32_t)(lane >> 4) * 16;                 // k-half
    const uint32_t brow_b = (uint32_t)(wn * 32 + (lane & 7) + ((lane >> 4) << 3)) * 128;
    const uint32_t bchk   = (uint32_t)((lane >> 3) & 1) * 16;

    // staging / store mapping: v = tid + i*256 -> row = v>>3, chunk = v&7
    float4 xa[4], xb[4];

    float acc[4][4][4];
#pragma unroll
    for (int i = 0; i < 4; i++)
#pragma unroll
        for (int j = 0; j < 4; j++)
#pragma unroll
            for (int r = 0; r < 4; r++) acc[i][j][r] = 0.0f;

    auto ldg = [&](int c) {
#pragma unroll
        for (int i = 0; i < 4; i++) {
            const int v   = tid + (i << 8);
            const int row = v >> 3;
            const int ch  = v & 7;
            xa[i] = *reinterpret_cast<const float4*>(
                X + (size_t)(m0 + row) * DMODEL + c * GK + ch * 4);
            xb[i] = *reinterpret_cast<const float4*>(
                W + (size_t)(n0 + row) * DMODEL + c * GK + ch * 4);
        }
    };

    auto sts = [&](int b) {
        char* sa = smem + b * 2 * TILE_BYTES;
        char* sb = sa + TILE_BYTES;
#pragma unroll
        for (int i = 0; i < 4; i++) {
            const int v   = tid + (i << 8);
            const int row = v >> 3;
            const int ch  = v & 7;
            const uint32_t off = swz((uint32_t)(row * 128 + ch * 16));
            float4 at = make_float4(to_tf32(xa[i].x), to_tf32(xa[i].y),
                                    to_tf32(xa[i].z), to_tf32(xa[i].w));
            float4 bt = make_float4(to_tf32(xb[i].x), to_tf32(xb[i].y),
                                    to_tf32(xb[i].z), to_tf32(xb[i].w));
            *reinterpret_cast<float4*>(sa + off) = at;
            *reinterpret_cast<float4*>(sb + off) = bt;
        }
    };

    ldg(0);

    for (int c = 0; c < DMODEL / GK; c++) {
        const int b = c & 1;
        sts(b);
        __syncthreads();
        if (c + 1 < DMODEL / GK) ldg(c + 1);

        const uint32_t a_base = sbase + b * 2 * TILE_BYTES;
        const uint32_t b_base = a_base + TILE_BYTES;

#pragma unroll
        for (int s = 0; s < 4; s++) {           // k8 steps within BK=32
            uint32_t bf[4][2];                  // 4 n8 tiles x {b0,b1}
#pragma unroll
            for (int nb = 0; nb < 2; nb++) {
                uint32_t r0, r1, r2, r3;
                const uint32_t off = swz(brow_b + (uint32_t)nb * 2048 + s * 32 + bchk);
                ldmatrix_x4(r0, r1, r2, r3, b_base + off);
                bf[nb * 2 + 0][0] = r0; bf[nb * 2 + 0][1] = r1;
                bf[nb * 2 + 1][0] = r2; bf[nb * 2 + 1][1] = r3;
            }
#pragma unroll
            for (int i = 0; i < 4; i++) {       // 4 m16 tiles
                uint32_t a0, a1, a2, a3;
                const uint32_t off = swz(arow_b + (uint32_t)i * 2048 + s * 32 + achk);
                ldmatrix_x4(a0, a1, a2, a3, a_base + off);
#pragma unroll
                for (int j = 0; j < 4; j++)
                    mma_tf32(acc[i][j][0], acc[i][j][1], acc[i][j][2], acc[i][j][3],
                             a0, a1, a2, a3, bf[j][0], bf[j][1]);
            }
        }
        __syncthreads();
    }

    // Epilogue: thread (g = lane>>2, t = lane&3)
    const int g = lane >> 2;
    const int t = lane & 3;
    float bb2[4][2];
#pragma unroll
    for (int j = 0; j < 4; j++) {
        const int n = n0 + wn * 32 + j * 8 + 2 * t;
        bb2[j][0] = bias[n];
        bb2[j][1] = bias[n + 1];
    }

#pragma unroll
    for (int i = 0; i < 4; i++) {
#pragma unroll
        for (int half = 0; half < 2; half++) {
            const int m = m0 + wm * 64 + i * 16 + g + half * 8;
#pragma unroll
            for (int j = 0; j < 4; j++) {
                const int n = n0 + wn * 32 + j * 8 + 2 * t;
                float2 r;
                r.x = acc[i][j][half * 2 + 0] + bb2[j][0];
                r.y = acc[i][j][half * 2 + 1] + bb2[j][1];
                size_t idx;
                if (LAYOUT == 0) {
                    idx = (size_t)m * DMODEL + n;
                } else {
                    const int bbk = m / S;
                    const int s   = m - bbk * S;
                    const int h   = n >> 6;
                    const int d   = n & 63;
                    idx = (((size_t)bbk * NHEADS + h) * S + s) * 64 + d;
                }
                *reinterpret_cast<float2*>(Y + idx) = r;
            }
        }
    }
}

// ---------------------------------------------------------------------------
// Flash attention (unchanged fp32 SIMT this round): per (b,h),
// out = softmax(Q K^T / 8) V.  Grid: (SQ/64, B*H). Block: 256 threads.
// ---------------------------------------------------------------------------
__global__ __launch_bounds__(256)
void attn_kernel(const float* __restrict__ Q, const float* __restrict__ K,
                 const float* __restrict__ V, float* __restrict__ out)
{
    __shared__ __align__(16) float Qs[64 * 68];
    __shared__ __align__(16) float KP[64 * 36];
    __shared__ __align__(16) float Vs[32 * 64];

    const int tid = threadIdx.x;
    const int tx  = tid & 15;
    const int ty  = tid >> 4;
    const int ty4 = ty * 4;
    const int tx2 = tx * 2;
    const int tx4 = tx * 4;

    const int bh = blockIdx.y;
    const int q0 = blockIdx.x * 64;

    const float* Qp = Q + ((size_t)bh * SQ + q0) * 64;
    const float* Kp = K + (size_t)bh * SKV * 64;
    const float* Vp = V + (size_t)bh * SKV * 64;

#pragma unroll
    for (int i = 0; i < 4; i++) {
        int v  = tid + (i << 8);
        int r  = v >> 4;
        int dq = (v & 15) << 2;
        const float4 q4 = *reinterpret_cast<const float4*>(Qp + (size_t)r * 64 + dq);
        Qs[(dq + 0) * 68 + r] = q4.x;
        Qs[(dq + 1) * 68 + r] = q4.y;
        Qs[(dq + 2) * 68 + r] = q4.z;
        Qs[(dq + 3) * 68 + r] = q4.w;
    }

    float m_i[4], l_i[4], o[4][4];
#pragma unroll
    for (int i = 0; i < 4; i++) {
        m_i[i] = -1e30f;
        l_i[i] = 0.0f;
#pragma unroll
        for (int j = 0; j < 4; j++) o[i][j] = 0.0f;
    }
    const float scale = 0.125f;

    for (int t = 0; t < SKV / 32; t++) {
        __syncthreads();
        const float* Kt = Kp + (size_t)t * 32 * 64;
        const float* Vt = Vp + (size_t)t * 32 * 64;
#pragma unroll
        for (int i = 0; i < 2; i++) {
            int v  = tid + (i << 8);
            int c  = v >> 4;
            int dq = (v & 15) << 2;
            const float4 k4 = *reinterpret_cast<const float4*>(Kt + (size_t)c * 64 + dq);
            KP[(dq + 0) * 36 + c] = k4.x;
            KP[(dq + 1) * 36 + c] = k4.y;
            KP[(dq + 2) * 36 + c] = k4.z;
            KP[(dq + 3) * 36 + c] = k4.w;
            const float4 v4 = *reinterpret_cast<const float4*>(Vt + (size_t)c * 64 + dq);
            *reinterpret_cast<float4*>(&Vs[c * 64 + dq]) = v4;
        }
        __syncthreads();

        float s[4][2];
#pragma unroll
        for (int i = 0; i < 4; i++) { s[i][0] = 0.0f; s[i][1] = 0.0f; }
#pragma unroll
        for (int d = 0; d < 64; d++) {
            float4 a  = *reinterpret_cast<const float4*>(&Qs[d * 68 + ty4]);
            float2 bv = *reinterpret_cast<const float2*>(&KP[d * 36 + tx2]);
            float av[4] = {a.x, a.y, a.z, a.w};
#pragma unroll
            for (int i = 0; i < 4; i++) {
                s[i][0] = fmaf(av[i], bv.x, s[i][0]);
                s[i][1] = fmaf(av[i], bv.y, s[i][1]);
            }
        }

        float mt[4];
#pragma unroll
        for (int i = 0; i < 4; i++) {
            s[i][0] *= scale; s[i][1] *= scale;
            mt[i] = fmaxf(s[i][0], s[i][1]);
        }
#pragma unroll
        for (int off = 1; off < 16; off <<= 1)
#pragma unroll
            for (int i = 0; i < 4; i++)
                mt[i] = fmaxf(mt[i], __shfl_xor_sync(0xffffffffu, mt[i], off));

        float p[4][2], rs[4], alpha[4];
#pragma unroll
        for (int i = 0; i < 4; i++) {
            float m_new = fmaxf(m_i[i], mt[i]);
            alpha[i] = __expf(m_i[i] - m_new);
            p[i][0] = __expf(s[i][0] - m_new);
            p[i][1] = __expf(s[i][1] - m_new);
            rs[i] = p[i][0] + p[i][1];
            m_i[i] = m_new;
        }
#pragma unroll
        for (int off = 1; off < 16; off <<= 1)
#pragma unroll
            for (int i = 0; i < 4; i++)
                rs[i] += __shfl_xor_sync(0xffffffffu, rs[i], off);
#pragma unroll
        for (int i = 0; i < 4; i++) {
            l_i[i] = l_i[i] * alpha[i] + rs[i];
#pragma unroll
            for (int j = 0; j < 4; j++) o[i][j] *= alpha[i];
        }

        __syncthreads();

#pragma unroll
        for (int j = 0; j < 2; j++) {
            float4 pv = make_float4(p[0][j], p[1][j], p[2][j], p[3][j]);
            *reinterpret_cast<float4*>(&KP[(tx2 + j) * 68 + ty4]) = pv;
        }
        __syncthreads();

#pragma unroll
        for (int c = 0; c < 32; c++) {
            float4 a  = *reinterpret_cast<const float4*>(&KP[c * 68 + ty4]);
            float4 bv = *reinterpret_cast<const float4*>(&Vs[c * 64 + tx4]);
            float av[4] = {a.x, a.y, a.z, a.w};
            float bb[4] = {bv.x, bv.y, bv.z, bv.w};
#pragma unroll
            for (int i = 0; i < 4; i++)
#pragma unroll
                for (int j = 0; j < 4; j++)
                    o[i][j] = fmaf(av[i], bb[j], o[i][j]);
        }
    }

    const int b = bh >> 4;
    const int h = bh & 15;
    const size_t row_base = (size_t)b * SQ + q0 + ty4;
#pragma unroll
    for (int i = 0; i < 4; i++) {
        float inv = 1.0f / l_i[i];
        float4 r = make_float4(o[i][0] * inv, o[i][1] * inv,
                               o[i][2] * inv, o[i][3] * inv);
        *reinterpret_cast<float4*>(out + (row_base + i) * 1024 + h * 64 + tx4) = r;
    }
}

// ---------------------------------------------------------------------------
extern "C" void kernel_launch(void* const* d_in, const int* in_sizes, int n_in,
                              void* d_out, int out_size)
{
    (void)in_sizes; (void)n_in; (void)out_size;
    const float* query = (const float*)d_in[0];
    const float* keyval = (const float*)d_in[1];
    const float* Wq = (const float*)d_in[2];
    const float* bq = (const float*)d_in[3];
    const float* Wk = (const float*)d_in[4];
    const float* bk = (const float*)d_in[5];
    const float* Wv = (const float*)d_in[6];
    const float* bv = (const float*)d_in[7];
    const float* Wo = (const float*)d_in[8];
    const float* bo = (const float*)d_in[9];
    float* out = (float*)d_out;

    float *qbuf, *kbuf, *vbuf, *abuf;
    cudaGetSymbolAddress((void**)&qbuf, g_Q);
    cudaGetSymbolAddress((void**)&kbuf, g_K);
    cudaGetSymbolAddress((void**)&vbuf, g_V);
    cudaGetSymbolAddress((void**)&abuf, g_attn);

    cudaFuncSetAttribute(gemm_hmma_kernel<0>,
                         cudaFuncAttributeMaxDynamicSharedMemorySize, SM_TOTAL_G);
    cudaFuncSetAttribute(gemm_hmma_kernel<1>,
                         cudaFuncAttributeMaxDynamicSharedMemorySize, SM_TOTAL_G);

    dim3 blk(256);
    dim3 grid_proj(DMODEL / 128, (BB * SQ) / 128);   // (8, 64)

    gemm_hmma_kernel<1><<<grid_proj, blk, SM_TOTAL_G>>>(query,  Wq, bq, qbuf, SQ);
    gemm_hmma_kernel<1><<<grid_proj, blk, SM_TOTAL_G>>>(keyval, Wk, bk, kbuf, SKV);
    gemm_hmma_kernel<1><<<grid_proj, blk, SM_TOTAL_G>>>(keyval, Wv, bv, vbuf, SKV);

    dim3 grid_attn(SQ / 64, BB * NHEADS); // (32, 64)
    attn_kernel<<<grid_attn, blk>>>(qbuf, kbuf, vbuf, abuf);

    gemm_hmma_kernel<0><<<grid_proj, blk, SM_TOTAL_G>>>(abuf, Wo, bo, out, SQ);
}

// round 5
// speedup vs baseline: 2.9374x; 2.1030x over previous
#include <cuda_runtime.h>
#include <cstdint>
#include <math.h>

// Fixed problem shape
#define BB       4
#define SQ       2048
#define SKV      2048
#define DMODEL   1024
#define NHEADS   16
#define HDIM     64

// Scratch (device globals; no allocation allowed)
__device__ float g_Q[BB * NHEADS * SQ * HDIM];     // [B,H,SQ,Dh]
__device__ float g_K[BB * NHEADS * SKV * HDIM];    // [B,H,SKV,Dh]
__device__ float g_V[BB * NHEADS * SKV * HDIM];    // [B,H,SKV,Dh]
__device__ float g_attn[BB * SQ * DMODEL];         // [B*SQ, D]

// ===========================================================================
// Helpers: tf32 round, ldmatrix, mma (all base-target PTX, sm_80+)
// ===========================================================================
__device__ __forceinline__ float to_tf32(float x) {
    uint32_t r;
    asm("cvt.rna.tf32.f32 %0, %1;" : "=r"(r) : "f"(x));
    return __uint_as_float(r);
}
__device__ __forceinline__ float4 tf32x4(float4 v) {
    return make_float4(to_tf32(v.x), to_tf32(v.y), to_tf32(v.z), to_tf32(v.w));
}

__device__ __forceinline__ void ldmatrix_x4(uint32_t& r0, uint32_t& r1,
                                            uint32_t& r2, uint32_t& r3,
                                            uint32_t addr) {
    asm volatile("ldmatrix.sync.aligned.m8n8.x4.shared.b16 {%0,%1,%2,%3}, [%4];"
                 : "=r"(r0), "=r"(r1), "=r"(r2), "=r"(r3) : "r"(addr));
}

__device__ __forceinline__ void mma_tf32(float& c0, float& c1, float& c2, float& c3,
                                         uint32_t a0, uint32_t a1, uint32_t a2, uint32_t a3,
                                         uint32_t b0, uint32_t b1) {
    asm volatile(
        "mma.sync.aligned.m16n8k8.row.col.f32.tf32.tf32.f32 "
        "{%0,%1,%2,%3}, {%4,%5,%6,%7}, {%8,%9}, {%0,%1,%2,%3};"
        : "+f"(c0), "+f"(c1), "+f"(c2), "+f"(c3)
        : "r"(a0), "r"(a1), "r"(a2), "r"(a3), "r"(b0), "r"(b1));
}

__device__ __forceinline__ uint32_t smem_u32(const void* p) {
    return (uint32_t)__cvta_generic_to_shared(p);
}

// XOR swizzle on 16B chunks within a 128B row (rows of 32 f32)
__device__ __forceinline__ uint32_t swz(uint32_t off) {
    return off ^ ((off >> 3) & 0x70);
}

// ===========================================================================
// HMMA tf32 GEMM: Y = X @ W^T + bias.  (unchanged from R3 — passing)
// ===========================================================================
#define GK 32
#define TILE_BYTES (128 * GK * 4)
#define SM_TOTAL_G (4 * TILE_BYTES)

template <int LAYOUT>
__global__ __launch_bounds__(256)
void gemm_hmma_kernel(const float* __restrict__ X, const float* __restrict__ W,
                      const float* __restrict__ bias, float* __restrict__ Y, int S)
{
    extern __shared__ __align__(128) char smem[];
    const uint32_t sbase = smem_u32(smem);

    const int tid  = threadIdx.x;
    const int wid  = tid >> 5;
    const int lane = tid & 31;
    const int wm   = wid >> 2;
    const int wn   = wid & 3;
    const int m0   = blockIdx.y * 128;
    const int n0   = blockIdx.x * 128;

    const uint32_t arow_b = (uint32_t)(wm * 64 + (lane & 15)) * 128;
    const uint32_t achk   = (uint32_t)(lane >> 4) * 16;
    const uint32_t brow_b = (uint32_t)(wn * 32 + (lane & 7) + ((lane >> 4) << 3)) * 128;
    const uint32_t bchk   = (uint32_t)((lane >> 3) & 1) * 16;

    float4 xa[4], xb[4];

    float acc[4][4][4];
#pragma unroll
    for (int i = 0; i < 4; i++)
#pragma unroll
        for (int j = 0; j < 4; j++)
#pragma unroll
            for (int r = 0; r < 4; r++) acc[i][j][r] = 0.0f;

    auto ldg = [&](int c) {
#pragma unroll
        for (int i = 0; i < 4; i++) {
            const int v   = tid + (i << 8);
            const int row = v >> 3;
            const int ch  = v & 7;
            xa[i] = *reinterpret_cast<const float4*>(
                X + (size_t)(m0 + row) * DMODEL + c * GK + ch * 4);
            xb[i] = *reinterpret_cast<const float4*>(
                W + (size_t)(n0 + row) * DMODEL + c * GK + ch * 4);
        }
    };

    auto sts = [&](int b) {
        char* sa = smem + b * 2 * TILE_BYTES;
        char* sb = sa + TILE_BYTES;
#pragma unroll
        for (int i = 0; i < 4; i++) {
            const int v   = tid + (i << 8);
            const int row = v >> 3;
            const int ch  = v & 7;
            const uint32_t off = swz((uint32_t)(row * 128 + ch * 16));
            *reinterpret_cast<float4*>(sa + off) = tf32x4(xa[i]);
            *reinterpret_cast<float4*>(sb + off) = tf32x4(xb[i]);
        }
    };

    ldg(0);

    for (int c = 0; c < DMODEL / GK; c++) {
        const int b = c & 1;
        sts(b);
        __syncthreads();
        if (c + 1 < DMODEL / GK) ldg(c + 1);

        const uint32_t a_base = sbase + b * 2 * TILE_BYTES;
        const uint32_t b_base = a_base + TILE_BYTES;

#pragma unroll
        for (int s = 0; s < 4; s++) {
            uint32_t bf[4][2];
#pragma unroll
            for (int nb = 0; nb < 2; nb++) {
                uint32_t r0, r1, r2, r3;
                const uint32_t off = swz(brow_b + (uint32_t)nb * 2048 + s * 32 + bchk);
                ldmatrix_x4(r0, r1, r2, r3, b_base + off);
                bf[nb * 2 + 0][0] = r0; bf[nb * 2 + 0][1] = r1;
                bf[nb * 2 + 1][0] = r2; bf[nb * 2 + 1][1] = r3;
            }
#pragma unroll
            for (int i = 0; i < 4; i++) {
                uint32_t a0, a1, a2, a3;
                const uint32_t off = swz(arow_b + (uint32_t)i * 2048 + s * 32 + achk);
                ldmatrix_x4(a0, a1, a2, a3, a_base + off);
#pragma unroll
                for (int j = 0; j < 4; j++)
                    mma_tf32(acc[i][j][0], acc[i][j][1], acc[i][j][2], acc[i][j][3],
                             a0, a1, a2, a3, bf[j][0], bf[j][1]);
            }
        }
        __syncthreads();
    }

    const int g = lane >> 2;
    const int t = lane & 3;
    float bb2[4][2];
#pragma unroll
    for (int j = 0; j < 4; j++) {
        const int n = n0 + wn * 32 + j * 8 + 2 * t;
        bb2[j][0] = bias[n];
        bb2[j][1] = bias[n + 1];
    }

#pragma unroll
    for (int i = 0; i < 4; i++) {
#pragma unroll
        for (int half = 0; half < 2; half++) {
            const int m = m0 + wm * 64 + i * 16 + g + half * 8;
#pragma unroll
            for (int j = 0; j < 4; j++) {
                const int n = n0 + wn * 32 + j * 8 + 2 * t;
                float2 r;
                r.x = acc[i][j][half * 2 + 0] + bb2[j][0];
                r.y = acc[i][j][half * 2 + 1] + bb2[j][1];
                size_t idx;
                if (LAYOUT == 0) {
                    idx = (size_t)m * DMODEL + n;
                } else {
                    const int bbk = m / S;
                    const int s   = m - bbk * S;
                    const int h   = n >> 6;
                    const int d   = n & 63;
                    idx = (((size_t)bbk * NHEADS + h) * S + s) * 64 + d;
                }
                *reinterpret_cast<float2*>(Y + idx) = r;
            }
        }
    }
}

// ===========================================================================
// HMMA tf32 flash attention.
// Grid (SQ/128, B*H), 256 threads = 8 warps. BQ=128 (16 q rows/warp), BKV=64.
// Smem: QP[128][68] (Q, later P; rows private per warp), Ks[64][68], Vt[64][68].
// Each warp: S(16x64) = Qfrag x K, online softmax (quad shfl only),
// P -> own smem rows -> ldmatrix A frags, O(16x64) += P x Vt.
// ===========================================================================
#define SR 68
#define SM_ATTN ((128 + 64 + 64) * SR * 4)   // 69632 B

__global__ __launch_bounds__(256)
void attn_hmma_kernel(const float* __restrict__ Q, const float* __restrict__ K,
                      const float* __restrict__ V, float* __restrict__ out)
{
    extern __shared__ __align__(16) float sm[];
    float* QP = sm;                    // 128 x SR (Q then P)
    float* Ks = sm + 128 * SR;         // 64 x SR
    float* Vt = Ks + 64 * SR;          // 64 x SR  (Vt[d][kv])

    const int tid  = threadIdx.x;
    const int wid  = tid >> 5;
    const int lane = tid & 31;
    const int g    = lane >> 2;
    const int t    = lane & 3;
    const int bh   = blockIdx.y;
    const int q0   = blockIdx.x * 128;

    const float* Qp = Q + ((size_t)bh * SQ + q0) * 64;
    const float* Kp = K + (size_t)bh * SKV * 64;
    const float* Vp = V + (size_t)bh * SKV * 64;

    // Load Q tile (tf32-rounded)
#pragma unroll
    for (int i = 0; i < 8; i++) {
        const int v   = tid + (i << 8);
        const int row = v >> 4;
        const int c4  = v & 15;
        const float4 q4 = *reinterpret_cast<const float4*>(Qp + (size_t)row * 64 + c4 * 4);
        *reinterpret_cast<float4*>(QP + row * SR + c4 * 4) = tf32x4(q4);
    }
    __syncthreads();

    // Per-warp ldmatrix bases
    const uint32_t abase = smem_u32(QP + (16 * wid + (lane & 15)) * SR) + ((lane >> 4) << 4);
    const uint32_t kbase = smem_u32(Ks + ((lane & 7) + ((lane >> 4) << 3)) * SR)
                           + (((lane >> 3) & 1) << 4);
    const uint32_t vbase = smem_u32(Vt + ((lane & 7) + ((lane >> 4) << 3)) * SR)
                           + (((lane >> 3) & 1) << 4);

    // Cache Q fragments (Q smem becomes dead -> reused for P)
    uint32_t qf[8][4];
#pragma unroll
    for (int s = 0; s < 8; s++)
        ldmatrix_x4(qf[s][0], qf[s][1], qf[s][2], qf[s][3], abase + s * 32);

    float m_[2] = {-1e30f, -1e30f};
    float l_[2] = {0.0f, 0.0f};
    float o[8][4];
#pragma unroll
    for (int j = 0; j < 8; j++)
#pragma unroll
        for (int r = 0; r < 4; r++) o[j][r] = 0.0f;

    const int vrow = tid & 63;
    const int cg   = tid >> 6;

    for (int tile = 0; tile < SKV / 64; tile++) {
        __syncthreads();   // everyone done reading Ks/Vt of previous tile
        const float* Kt = Kp + (size_t)tile * 64 * 64;
        const float* Vtl = Vp + (size_t)tile * 64 * 64;
#pragma unroll
        for (int i = 0; i < 4; i++) {
            const int v   = tid + (i << 8);
            const int row = v >> 4;
            const int c4  = v & 15;
            const float4 k4 = *reinterpret_cast<const float4*>(Kt + (size_t)row * 64 + c4 * 4);
            *reinterpret_cast<float4*>(Ks + row * SR + c4 * 4) = tf32x4(k4);
            const int ch = cg * 4 + i;
            const float4 v4 = *reinterpret_cast<const float4*>(Vtl + (size_t)vrow * 64 + ch * 4);
            Vt[(ch * 4 + 0) * SR + vrow] = to_tf32(v4.x);
            Vt[(ch * 4 + 1) * SR + vrow] = to_tf32(v4.y);
            Vt[(ch * 4 + 2) * SR + vrow] = to_tf32(v4.z);
            Vt[(ch * 4 + 3) * SR + vrow] = to_tf32(v4.w);
        }
        __syncthreads();

        // S = Q K^T  (16 x 64 per warp)
        float sa[8][4];
#pragma unroll
        for (int j = 0; j < 8; j++)
#pragma unroll
            for (int r = 0; r < 4; r++) sa[j][r] = 0.0f;
#pragma unroll
        for (int s = 0; s < 8; s++) {
#pragma unroll
            for (int nb = 0; nb < 4; nb++) {
                uint32_t r0, r1, r2, r3;
                ldmatrix_x4(r0, r1, r2, r3, kbase + (uint32_t)nb * (16 * SR * 4) + s * 32);
                mma_tf32(sa[2*nb][0], sa[2*nb][1], sa[2*nb][2], sa[2*nb][3],
                         qf[s][0], qf[s][1], qf[s][2], qf[s][3], r0, r1);
                mma_tf32(sa[2*nb+1][0], sa[2*nb+1][1], sa[2*nb+1][2], sa[2*nb+1][3],
                         qf[s][0], qf[s][1], qf[s][2], qf[s][3], r2, r3);
            }
        }

        // Online softmax. Row g: sa[j][0..1], row g+8: sa[j][2..3].
        const float scale = 0.125f;
        float mx0 = -1e30f, mx1 = -1e30f;
#pragma unroll
        for (int j = 0; j < 8; j++) {
            sa[j][0] *= scale; sa[j][1] *= scale;
            sa[j][2] *= scale; sa[j][3] *= scale;
            mx0 = fmaxf(mx0, fmaxf(sa[j][0], sa[j][1]));
            mx1 = fmaxf(mx1, fmaxf(sa[j][2], sa[j][3]));
        }
        mx0 = fmaxf(mx0, __shfl_xor_sync(0xffffffffu, mx0, 1));
        mx0 = fmaxf(mx0, __shfl_xor_sync(0xffffffffu, mx0, 2));
        mx1 = fmaxf(mx1, __shfl_xor_sync(0xffffffffu, mx1, 1));
        mx1 = fmaxf(mx1, __shfl_xor_sync(0xffffffffu, mx1, 2));

        const float mn0 = fmaxf(m_[0], mx0);
        const float mn1 = fmaxf(m_[1], mx1);
        const float al0 = __expf(m_[0] - mn0);
        const float al1 = __expf(m_[1] - mn1);
        m_[0] = mn0; m_[1] = mn1;

        float rs0 = 0.0f, rs1 = 0.0f;
#pragma unroll
        for (int j = 0; j < 8; j++) {
            sa[j][0] = __expf(sa[j][0] - mn0);
            sa[j][1] = __expf(sa[j][1] - mn0);
            sa[j][2] = __expf(sa[j][2] - mn1);
            sa[j][3] = __expf(sa[j][3] - mn1);
            rs0 += sa[j][0] + sa[j][1];
            rs1 += sa[j][2] + sa[j][3];
        }
        rs0 += __shfl_xor_sync(0xffffffffu, rs0, 1);
        rs0 += __shfl_xor_sync(0xffffffffu, rs0, 2);
        rs1 += __shfl_xor_sync(0xffffffffu, rs1, 1);
        rs1 += __shfl_xor_sync(0xffffffffu, rs1, 2);
        l_[0] = l_[0] * al0 + rs0;
        l_[1] = l_[1] * al1 + rs1;
#pragma unroll
        for (int j = 0; j < 8; j++) {
            o[j][0] *= al0; o[j][1] *= al0;
            o[j][2] *= al1; o[j][3] *= al1;
        }

        // Store P (tf32) into own warp's rows of QP
        float* prow0 = QP + (16 * wid + g) * SR;
        float* prow1 = prow0 + 8 * SR;
#pragma unroll
        for (int j = 0; j < 8; j++) {
            *reinterpret_cast<float2*>(prow0 + j * 8 + 2 * t) =
                make_float2(to_tf32(sa[j][0]), to_tf32(sa[j][1]));
            *reinterpret_cast<float2*>(prow1 + j * 8 + 2 * t) =
                make_float2(to_tf32(sa[j][2]), to_tf32(sa[j][3]));
        }
        __syncwarp();

        // O += P * Vt
#pragma unroll
        for (int s = 0; s < 8; s++) {
            uint32_t a0, a1, a2, a3;
            ldmatrix_x4(a0, a1, a2, a3, abase + s * 32);
#pragma unroll
            for (int nb = 0; nb < 4; nb++) {
                uint32_t r0, r1, r2, r3;
                ldmatrix_x4(r0, r1, r2, r3, vbase + (uint32_t)nb * (16 * SR * 4) + s * 32);
                mma_tf32(o[2*nb][0], o[2*nb][1], o[2*nb][2], o[2*nb][3],
                         a0, a1, a2, a3, r0, r1);
                mma_tf32(o[2*nb+1][0], o[2*nb+1][1], o[2*nb+1][2], o[2*nb+1][3],
                         a0, a1, a2, a3, r2, r3);
            }
        }
        __syncwarp();   // P reads done before next tile's (no-op safety)
    }

    // Epilogue -> g_attn [B*SQ, 1024]
    const int b = bh >> 4;
    const int h = bh & 15;
    const float inv0 = 1.0f / l_[0];
    const float inv1 = 1.0f / l_[1];
    const size_t row0 = (size_t)b * SQ + q0 + 16 * wid + g;
#pragma unroll
    for (int j = 0; j < 8; j++) {
        const int col = h * 64 + j * 8 + 2 * t;
        *reinterpret_cast<float2*>(out + row0 * DMODEL + col) =
            make_float2(o[j][0] * inv0, o[j][1] * inv0);
        *reinterpret_cast<float2*>(out + (row0 + 8) * DMODEL + col) =
            make_float2(o[j][2] * inv1, o[j][3] * inv1);
    }
}

// ---------------------------------------------------------------------------
extern "C" void kernel_launch(void* const* d_in, const int* in_sizes, int n_in,
                              void* d_out, int out_size)
{
    (void)in_sizes; (void)n_in; (void)out_size;
    const float* query = (const float*)d_in[0];
    const float* keyval = (const float*)d_in[1];
    const float* Wq = (const float*)d_in[2];
    const float* bq = (const float*)d_in[3];
    const float* Wk = (const float*)d_in[4];
    const float* bk = (const float*)d_in[5];
    const float* Wv = (const float*)d_in[6];
    const float* bv = (const float*)d_in[7];
    const float* Wo = (const float*)d_in[8];
    const float* bo = (const float*)d_in[9];
    float* out = (float*)d_out;

    float *qbuf, *kbuf, *vbuf, *abuf;
    cudaGetSymbolAddress((void**)&qbuf, g_Q);
    cudaGetSymbolAddress((void**)&kbuf, g_K);
    cudaGetSymbolAddress((void**)&vbuf, g_V);
    cudaGetSymbolAddress((void**)&abuf, g_attn);

    cudaFuncSetAttribute(gemm_hmma_kernel<0>,
                         cudaFuncAttributeMaxDynamicSharedMemorySize, SM_TOTAL_G);
    cudaFuncSetAttribute(gemm_hmma_kernel<1>,
                         cudaFuncAttributeMaxDynamicSharedMemorySize, SM_TOTAL_G);
    cudaFuncSetAttribute(attn_hmma_kernel,
                         cudaFuncAttributeMaxDynamicSharedMemorySize, SM_ATTN);

    dim3 blk(256);
    dim3 grid_proj(DMODEL / 128, (BB * SQ) / 128);   // (8, 64)

    gemm_hmma_kernel<1><<<grid_proj, blk, SM_TOTAL_G>>>(query,  Wq, bq, qbuf, SQ);
    gemm_hmma_kernel<1><<<grid_proj, blk, SM_TOTAL_G>>>(keyval, Wk, bk, kbuf, SKV);
    gemm_hmma_kernel<1><<<grid_proj, blk, SM_TOTAL_G>>>(keyval, Wv, bv, vbuf, SKV);

    dim3 grid_attn(SQ / 128, BB * NHEADS); // (16, 64)
    attn_hmma_kernel<<<grid_attn, blk, SM_ATTN>>>(qbuf, kbuf, vbuf, abuf);

    gemm_hmma_kernel<0><<<grid_proj, blk, SM_TOTAL_G>>>(abuf, Wo, bo, out, SQ);
}